// round 12
// baseline (speedup 1.0000x reference)
#include <cuda_runtime.h>
#include <cuda_bf16.h>
#include <math.h>
#include <stdint.h>

#define NN 8192
#define PP 128
#define DD 256

// ---------------- device scratch (static globals — no runtime alloc) ----------
__device__ __nv_bfloat16 g_Mt[384 * NN];            // Mᵀ bf16: rows 0-127 = Pᵀ, 128-383 = Xnᵀ
__device__ double g_acc[2];                         // 0: coherence, 1: structure+weight SSE
__device__ unsigned int g_done;                     // finisher ticket

// ---------------------------------------------------------------------------
__device__ __forceinline__ uint32_t smem_u32(const void* p) {
    return (uint32_t)__cvta_generic_to_shared(p);
}
__device__ __forceinline__ void cpasync16(uint32_t dst, const void* src) {
    asm volatile("cp.async.cg.shared.global [%0], [%1], 16;"
                 :: "r"(dst), "l"(src) : "memory");
}
#define CP_COMMIT() asm volatile("cp.async.commit_group;" ::: "memory")
#define CP_WAIT0()  asm volatile("cp.async.wait_group 0;" ::: "memory")

// block reduce for up to 512 threads
__device__ __forceinline__ float block_reduce_sum(float v) {
    __shared__ float red[16];
    int lane = threadIdx.x & 31;
    int wid  = threadIdx.x >> 5;
    #pragma unroll
    for (int o = 16; o > 0; o >>= 1) v += __shfl_xor_sync(0xffffffffu, v, o);
    if (lane == 0) red[wid] = v;
    __syncthreads();
    if (wid == 0) {
        int nw = (int)blockDim.x >> 5;
        v = (lane < nw) ? red[lane] : 0.0f;
        #pragma unroll
        for (int o = 8; o > 0; o >>= 1) v += __shfl_xor_sync(0xffffffffu, v, o);
    }
    return v;
}

// ---------------------------------------------------------------------------
// K_PREP (fused, 256 threads): X slabs -> norms -> scaled transposed Mt rows
// 128..383; P transpose -> Mt rows 0..127; zero block.
#define XSLAB_BLOCKS 128
#define PT_BLOCKS    256
#define PREP_GRID    (XSLAB_BLOCKS + PT_BLOCKS + 1)
#define XS 259
#define SMEM_PREP (64 * XS * 4 + 64 * 4)

__global__ void __launch_bounds__(256) k_prep(const float* __restrict__ X,
                                              const float* __restrict__ Pr) {
    extern __shared__ __align__(16) char dynsm[];
    int b = blockIdx.x;
    int t = threadIdx.x;
    int lane = t & 31;
    int wrp  = t >> 5;
    int tx = t & 15, ty = t >> 4;

    if (b < XSLAB_BLOCKS) {
        float* tt = (float*)dynsm;
        float* sI = (float*)(dynsm + 64 * XS * 4);
        int kb = b * 64;

        #pragma unroll
        for (int q = 0; q < 16; q++) {
            int c = t + q * 256;
            int row = c >> 6;
            int col = (c & 63) * 4;
            float4 v = *(const float4*)&X[(size_t)(kb + row) * DD + col];
            tt[row * XS + col + 0] = v.x;
            tt[row * XS + col + 1] = v.y;
            tt[row * XS + col + 2] = v.z;
            tt[row * XS + col + 3] = v.w;
        }
        __syncthreads();

        #pragma unroll
        for (int r8 = 0; r8 < 8; r8++) {
            int row = wrp * 8 + r8;
            float ss = 0.0f;
            #pragma unroll
            for (int j = 0; j < 8; j++) {
                float x = tt[row * XS + lane * 8 + j];
                ss += x * x;
            }
            #pragma unroll
            for (int o = 16; o > 0; o >>= 1) ss += __shfl_xor_sync(0xffffffffu, ss, o);
            if (lane == 0) sI[row] = 1.0f / fmaxf(sqrtf(ss), 1e-8f);
        }
        __syncthreads();

        #pragma unroll
        for (int dt = 0; dt < 4; dt++) {
            #pragma unroll
            for (int rr = ty; rr < 64; rr += 16) {
                int cc = tx * 4;
                int sc = dt * 64 + rr;
                float f0 = tt[(cc + 0) * XS + sc] * sI[cc + 0];
                float f1 = tt[(cc + 1) * XS + sc] * sI[cc + 1];
                float f2 = tt[(cc + 2) * XS + sc] * sI[cc + 2];
                float f3 = tt[(cc + 3) * XS + sc] * sI[cc + 3];
                __nv_bfloat162 lo = __floats2bfloat162_rn(f0, f1);
                __nv_bfloat162 hi = __floats2bfloat162_rn(f2, f3);
                uint2 o; o.x = *(uint32_t*)&lo; o.y = *(uint32_t*)&hi;
                *(uint2*)&g_Mt[(size_t)(128 + dt * 64 + rr) * NN + kb + cc] = o;
            }
        }
    } else if (b < XSLAB_BLOCKS + PT_BLOCKS) {
        float (*tt65)[65] = (float(*)[65])dynsm;
        int b2 = b - XSLAB_BLOCKS;
        int kb = (b2 >> 1) * 64;
        int pb = (b2 & 1) * 64;
        #pragma unroll
        for (int r = ty; r < 64; r += 16) {
            float4 v = *(const float4*)&Pr[(size_t)(kb + r) * PP + pb + tx * 4];
            tt65[r][tx * 4 + 0] = v.x;
            tt65[r][tx * 4 + 1] = v.y;
            tt65[r][tx * 4 + 2] = v.z;
            tt65[r][tx * 4 + 3] = v.w;
        }
        __syncthreads();
        #pragma unroll
        for (int rr = ty; rr < 64; rr += 16) {
            int cc = tx * 4;
            __nv_bfloat162 lo = __floats2bfloat162_rn(tt65[cc + 0][rr], tt65[cc + 1][rr]);
            __nv_bfloat162 hi = __floats2bfloat162_rn(tt65[cc + 2][rr], tt65[cc + 3][rr]);
            uint2 o; o.x = *(uint32_t*)&lo; o.y = *(uint32_t*)&hi;
            *(uint2*)&g_Mt[(size_t)(pb + rr) * NN + kb + cc] = o;
        }
    } else {
        if (t < 2) g_acc[t] = 0.0;
        if (t == 2) g_done = 0u;
    }
}

// ---------------------------------------------------------------------------
// MAIN: 128 structure + 18 gram CTAs, 512 threads, double-buffered smem,
// cp.async for all bf16 tile fills, one barrier per K-tile.
#define STRUCT_BLOCKS 128
#define GRAM_BLOCKS 18
#define GRID_MAIN (STRUCT_BLOCKS + GRAM_BLOCKS)

#define KT 64
#define APAD 72
#define SA_STAGE (64 * APAD)
#define SB_STAGE (128 * APAD)
#define SMEM_MAIN ((SA_STAGE + SB_STAGE) * 2 * 2)   // 55296 bytes

__device__ __forceinline__ void ldmx4(uint32_t& r0, uint32_t& r1, uint32_t& r2,
                                      uint32_t& r3, uint32_t addr) {
    asm volatile("ldmatrix.sync.aligned.m8n8.x4.shared.b16 {%0,%1,%2,%3}, [%4];"
                 : "=r"(r0), "=r"(r1), "=r"(r2), "=r"(r3) : "r"(addr));
}
__device__ __forceinline__ void mma_bf16(float* c, uint32_t a0, uint32_t a1,
                                         uint32_t a2, uint32_t a3,
                                         uint32_t b0, uint32_t b1) {
    asm volatile(
        "mma.sync.aligned.m16n8k16.row.col.f32.bf16.bf16.f32 "
        "{%0,%1,%2,%3}, {%4,%5,%6,%7}, {%8,%9}, {%0,%1,%2,%3};"
        : "+f"(c[0]), "+f"(c[1]), "+f"(c[2]), "+f"(c[3])
        : "r"(a0), "r"(a1), "r"(a2), "r"(a3), "r"(b0), "r"(b1));
}

template <bool GRAM>
__device__ __forceinline__ void gemm_body(const float* __restrict__ Af32,
                                          const __nv_bfloat16* __restrict__ Abf,
                                          const __nv_bfloat16* __restrict__ Bbf,
                                          const float* __restrict__ Pr,
                                          const float* __restrict__ W,
                                          int r_base, int c_base,
                                          __nv_bfloat16* sAb, __nv_bfloat16* sBb) {
    int tid  = threadIdx.x;             // 0..511
    int wid  = tid >> 5;
    int lane = tid & 31;
    int gid  = lane >> 2;
    int tid4 = lane & 3;
    int wm   = wid >> 2;                // 0..3 : 16-row slice
    int wn   = wid & 3;                 // 0..3 : 32-col slice

    int lrow = (lane & 7) + ((lane >> 3) & 1) * 8;
    int lk8  = (lane >> 4) * 8;

    uint32_t sA_u0 = smem_u32(sAb);
    uint32_t sB_u0 = smem_u32(sBb);

    float4 rA[2];    // structure A staging (fp32 -> bf16 conversion path)

    // structure A: register load (needs convert)
    auto loadA = [&](int it) {
        if (!GRAM) {
            int k0 = it * KT;
            #pragma unroll
            for (int q = 0; q < 2; q++) {
                int c = tid + q * 512;
                rA[q] = *(const float4*)&Af32[(size_t)(c >> 4) * NN + k0 + (c & 15) * 4];
            }
        }
    };
    auto storeA = [&](int buf) {
        if (!GRAM) {
            __nv_bfloat16* sA = sAb + buf * SA_STAGE;
            #pragma unroll
            for (int q = 0; q < 2; q++) {
                int c = tid + q * 512;
                __nv_bfloat162 lo = __floats2bfloat162_rn(rA[q].x, rA[q].y);
                __nv_bfloat162 hi = __floats2bfloat162_rn(rA[q].z, rA[q].w);
                uint2 o; o.x = *(uint32_t*)&lo; o.y = *(uint32_t*)&hi;
                *(uint2*)&sA[(c >> 4) * APAD + (c & 15) * 4] = o;
            }
        }
    };
    // bf16 fills via cp.async: B always; A too when GRAM
    auto issueAsync = [&](int it, int buf) {
        int k0 = it * KT;
        __nv_bfloat16* sB = sBb + buf * SB_STAGE;
        #pragma unroll
        for (int q = 0; q < 2; q++) {
            int c = tid + q * 512;                       // row = c>>3 (0..127), k-chunk = c&7
            cpasync16(smem_u32(&sB[(c >> 3) * APAD + (c & 7) * 8]),
                      &Bbf[(size_t)(c >> 3) * NN + k0 + (c & 7) * 8]);
        }
        if (GRAM) {
            __nv_bfloat16* sA = sAb + buf * SA_STAGE;
            int c = tid;                                 // row = c>>3 (0..63)
            cpasync16(smem_u32(&sA[(c >> 3) * APAD + (c & 7) * 8]),
                      &Abf[(size_t)(c >> 3) * NN + k0 + (c & 7) * 8]);
        }
        CP_COMMIT();
    };

    float acc[4][4] = {};

    const int NIT = NN / KT;   // 128

    // prologue: tile 0 in-flight, A regs for tile 1 staged
    loadA(0);
    issueAsync(0, 0);
    storeA(0);
    loadA(1);
    CP_WAIT0();
    __syncthreads();

    for (int it = 0; it < NIT; it++) {
        bool more = (it + 1 < NIT);
        if (more) {
            issueAsync(it + 1, (it + 1) & 1);
            storeA((it + 1) & 1);                        // rA holds tile it+1
        }
        if (it + 2 < NIT) loadA(it + 2);

        uint32_t aU = sA_u0 + (it & 1) * (SA_STAGE * 2);
        uint32_t bU = sB_u0 + (it & 1) * (SB_STAGE * 2);

        #pragma unroll
        for (int kk = 0; kk < KT; kk += 16) {
            uint32_t a0, a1, a2, a3;
            ldmx4(a0, a1, a2, a3,
                  aU + ((wm * 16 + lrow) * APAD + kk + lk8) * 2);
            #pragma unroll
            for (int nj = 0; nj < 2; nj++) {
                uint32_t b0, b1, b2, b3;
                ldmx4(b0, b1, b2, b3,
                      bU + ((wn * 32 + nj * 16 + lrow) * APAD + kk + lk8) * 2);
                mma_bf16(acc[nj * 2 + 0], a0, a1, a2, a3, b0, b2);
                mma_bf16(acc[nj * 2 + 1], a0, a1, a2, a3, b1, b3);
            }
        }
        if (more) CP_WAIT0();
        __syncthreads();
    }

    // epilogue
    float s = 0.0f;
    #pragma unroll
    for (int ni = 0; ni < 4; ni++) {
        int col = wn * 32 + ni * 8 + tid4 * 2;
        int m0  = wm * 16 + gid;
        if (!GRAM) {
            int m = r_base + m0;
            float p00 = Pr[(size_t)m * PP + col];
            float p01 = Pr[(size_t)m * PP + col + 1];
            float p10 = Pr[(size_t)(m + 8) * PP + col];
            float p11 = Pr[(size_t)(m + 8) * PP + col + 1];
            float d0 = p00 - acc[ni][0];
            float d1 = p01 - acc[ni][1];
            float d2 = p10 - acc[ni][2];
            float d3 = p11 - acc[ni][3];
            s += d0 * d0 + d1 * d1 + d2 * d2 + d3 * d3;
            float w00 = W[(size_t)m * PP + col];
            float w01 = W[(size_t)m * PP + col + 1];
            float w10 = W[(size_t)(m + 8) * PP + col];
            float w11 = W[(size_t)(m + 8) * PP + col + 1];
            float e0 = p00 - w00, e1 = p01 - w01, e2 = p10 - w10, e3 = p11 - w11;
            s += e0 * e0 + e1 * e1 + e2 * e2 + e3 * e3;
        } else {
            int r0g = r_base + m0;
            int r1g = r0g + 8;
            int c0g = c_base + col;
            int c1g = c0g + 1;
            float s00 = ((r0g < 128) == (c0g < 128)) ? 1.0f : -1.0f;
            float s01 = ((r0g < 128) == (c1g < 128)) ? 1.0f : -1.0f;
            float s10 = ((r1g < 128) == (c0g < 128)) ? 1.0f : -1.0f;
            float s11 = ((r1g < 128) == (c1g < 128)) ? 1.0f : -1.0f;
            s += s00 * acc[ni][0] * acc[ni][0] + s01 * acc[ni][1] * acc[ni][1]
               + s10 * acc[ni][2] * acc[ni][2] + s11 * acc[ni][3] * acc[ni][3];
        }
    }
    s = block_reduce_sum(s);
    if (tid == 0) atomicAdd(&g_acc[GRAM ? 0 : 1], (double)s);
}

__global__ void __launch_bounds__(512) k_main(const float* __restrict__ A,
                                              const float* __restrict__ Pr,
                                              const float* __restrict__ W,
                                              float* __restrict__ out) {
    extern __shared__ __align__(16) char dynsm[];
    __nv_bfloat16* sAb = (__nv_bfloat16*)dynsm;
    __nv_bfloat16* sBb = (__nv_bfloat16*)(dynsm + SA_STAGE * 2 * 2);

    int bid = blockIdx.x;
    if (bid < STRUCT_BLOCKS) {
        gemm_body<false>(A + (size_t)bid * 64 * NN, nullptr, g_Mt, Pr, W,
                         bid * 64, 0, sAb, sBb);
    } else {
        int g = bid - STRUCT_BLOCKS;
        int rblk = g / 3, cblk = g % 3;
        gemm_body<true>(nullptr,
                        g_Mt + (size_t)(rblk * 64) * NN,
                        g_Mt + (size_t)(cblk * 128) * NN,
                        Pr, nullptr, rblk * 64, cblk * 128, sAb, sBb);
    }

    __shared__ unsigned int s_ticket;
    __threadfence();
    if (threadIdx.x == 0) s_ticket = atomicAdd(&g_done, 1u);
    __syncthreads();
    if (s_ticket == GRID_MAIN - 1) {
        if (threadIdx.x == 0) {
            double nn = (double)NN * (double)NN;
            double np = (double)NN * (double)PP;
            out[0] = (float)(g_acc[0] / nn + g_acc[1] / np);
            g_done = 0u;
        }
    }
}

// ---------------------------------------------------------------------------
extern "C" void kernel_launch(void* const* d_in, const int* in_sizes, int n_in,
                              void* d_out, int out_size) {
    const float* preds = (const float*)d_in[0];   // [8192, 128]
    const float* emb   = (const float*)d_in[1];   // [8192, 256]
    const float* adj   = (const float*)d_in[2];   // [8192, 8192]
    const float* wts   = (const float*)d_in[3];   // [8192, 128]
    float* out = (float*)d_out;

    // idempotent; capture-safe (no alloc, no sync)
    cudaFuncSetAttribute(k_prep, cudaFuncAttributeMaxDynamicSharedMemorySize, SMEM_PREP);
    cudaFuncSetAttribute(k_main, cudaFuncAttributeMaxDynamicSharedMemorySize, SMEM_MAIN);

    k_prep<<<PREP_GRID, 256, SMEM_PREP>>>(emb, preds);
    k_main<<<GRID_MAIN, 512, SMEM_MAIN>>>(adj, preds, wts, out);
}

// round 13
// speedup vs baseline: 1.1267x; 1.1267x over previous
#include <cuda_runtime.h>
#include <cuda_bf16.h>
#include <math.h>
#include <stdint.h>

#define NN 8192
#define PP 128
#define DD 256

// ---------------- device scratch (static globals — no runtime alloc) ----------
__device__ __nv_bfloat16 g_Mt[384 * NN];            // Mᵀ bf16: rows 0-127 = Pᵀ, 128-383 = Xnᵀ
__device__ double g_acc[2];                         // 0: coherence, 1: structure+weight SSE
__device__ unsigned int g_done;                     // finisher ticket

// ---------------------------------------------------------------------------
__device__ __forceinline__ uint32_t smem_u32(const void* p) {
    return (uint32_t)__cvta_generic_to_shared(p);
}

// block reduce for up to 512 threads
__device__ __forceinline__ float block_reduce_sum(float v) {
    __shared__ float red[16];
    int lane = threadIdx.x & 31;
    int wid  = threadIdx.x >> 5;
    #pragma unroll
    for (int o = 16; o > 0; o >>= 1) v += __shfl_xor_sync(0xffffffffu, v, o);
    if (lane == 0) red[wid] = v;
    __syncthreads();
    if (wid == 0) {
        int nw = (int)blockDim.x >> 5;
        v = (lane < nw) ? red[lane] : 0.0f;
        #pragma unroll
        for (int o = 8; o > 0; o >>= 1) v += __shfl_xor_sync(0xffffffffu, v, o);
    }
    return v;
}

// ---------------------------------------------------------------------------
// K_PREP (fused, 256 threads): X slabs -> norms -> scaled transposed Mt rows
// 128..383; P transpose -> Mt rows 0..127; zero block.
#define XSLAB_BLOCKS 128
#define PT_BLOCKS    256
#define PREP_GRID    (XSLAB_BLOCKS + PT_BLOCKS + 1)
#define XS 259
#define SMEM_PREP (64 * XS * 4 + 64 * 4)

__global__ void __launch_bounds__(256) k_prep(const float* __restrict__ X,
                                              const float* __restrict__ Pr) {
    extern __shared__ __align__(16) char dynsm[];
    int b = blockIdx.x;
    int t = threadIdx.x;
    int lane = t & 31;
    int wrp  = t >> 5;
    int tx = t & 15, ty = t >> 4;

    if (b < XSLAB_BLOCKS) {
        float* tt = (float*)dynsm;
        float* sI = (float*)(dynsm + 64 * XS * 4);
        int kb = b * 64;

        #pragma unroll
        for (int q = 0; q < 16; q++) {
            int c = t + q * 256;
            int row = c >> 6;
            int col = (c & 63) * 4;
            float4 v = *(const float4*)&X[(size_t)(kb + row) * DD + col];
            tt[row * XS + col + 0] = v.x;
            tt[row * XS + col + 1] = v.y;
            tt[row * XS + col + 2] = v.z;
            tt[row * XS + col + 3] = v.w;
        }
        __syncthreads();

        #pragma unroll
        for (int r8 = 0; r8 < 8; r8++) {
            int row = wrp * 8 + r8;
            float ss = 0.0f;
            #pragma unroll
            for (int j = 0; j < 8; j++) {
                float x = tt[row * XS + lane * 8 + j];
                ss += x * x;
            }
            #pragma unroll
            for (int o = 16; o > 0; o >>= 1) ss += __shfl_xor_sync(0xffffffffu, ss, o);
            if (lane == 0) sI[row] = 1.0f / fmaxf(sqrtf(ss), 1e-8f);
        }
        __syncthreads();

        #pragma unroll
        for (int dt = 0; dt < 4; dt++) {
            #pragma unroll
            for (int rr = ty; rr < 64; rr += 16) {
                int cc = tx * 4;
                int sc = dt * 64 + rr;
                float f0 = tt[(cc + 0) * XS + sc] * sI[cc + 0];
                float f1 = tt[(cc + 1) * XS + sc] * sI[cc + 1];
                float f2 = tt[(cc + 2) * XS + sc] * sI[cc + 2];
                float f3 = tt[(cc + 3) * XS + sc] * sI[cc + 3];
                __nv_bfloat162 lo = __floats2bfloat162_rn(f0, f1);
                __nv_bfloat162 hi = __floats2bfloat162_rn(f2, f3);
                uint2 o; o.x = *(uint32_t*)&lo; o.y = *(uint32_t*)&hi;
                *(uint2*)&g_Mt[(size_t)(128 + dt * 64 + rr) * NN + kb + cc] = o;
            }
        }
    } else if (b < XSLAB_BLOCKS + PT_BLOCKS) {
        float (*tt65)[65] = (float(*)[65])dynsm;
        int b2 = b - XSLAB_BLOCKS;
        int kb = (b2 >> 1) * 64;
        int pb = (b2 & 1) * 64;
        #pragma unroll
        for (int r = ty; r < 64; r += 16) {
            float4 v = *(const float4*)&Pr[(size_t)(kb + r) * PP + pb + tx * 4];
            tt65[r][tx * 4 + 0] = v.x;
            tt65[r][tx * 4 + 1] = v.y;
            tt65[r][tx * 4 + 2] = v.z;
            tt65[r][tx * 4 + 3] = v.w;
        }
        __syncthreads();
        #pragma unroll
        for (int rr = ty; rr < 64; rr += 16) {
            int cc = tx * 4;
            __nv_bfloat162 lo = __floats2bfloat162_rn(tt65[cc + 0][rr], tt65[cc + 1][rr]);
            __nv_bfloat162 hi = __floats2bfloat162_rn(tt65[cc + 2][rr], tt65[cc + 3][rr]);
            uint2 o; o.x = *(uint32_t*)&lo; o.y = *(uint32_t*)&hi;
            *(uint2*)&g_Mt[(size_t)(pb + rr) * NN + kb + cc] = o;
        }
    } else {
        if (t < 2) g_acc[t] = 0.0;
        if (t == 2) g_done = 0u;
    }
}

// ---------------------------------------------------------------------------
// MAIN: 128 structure + 18 gram CTAs, 512 threads (16 warps = 2 wm x 4 wn x
// 2 kg), 32x32 warp tiles with 2-way K-split, double-buffered smem (LDG+STS),
// one barrier per K-tile, smem combine of kg partials before epilogue.
#define STRUCT_BLOCKS 128
#define GRAM_BLOCKS 18
#define GRID_MAIN (STRUCT_BLOCKS + GRAM_BLOCKS)

#define KT 64
#define APAD 72
#define SA_STAGE (64 * APAD)
#define SB_STAGE (128 * APAD)
#define SMEM_MAIN ((SA_STAGE + SB_STAGE) * 2 * 2)   // 55296 bytes

__device__ __forceinline__ void ldmx4(uint32_t& r0, uint32_t& r1, uint32_t& r2,
                                      uint32_t& r3, uint32_t addr) {
    asm volatile("ldmatrix.sync.aligned.m8n8.x4.shared.b16 {%0,%1,%2,%3}, [%4];"
                 : "=r"(r0), "=r"(r1), "=r"(r2), "=r"(r3) : "r"(addr));
}
__device__ __forceinline__ void mma_bf16(float* c, uint32_t a0, uint32_t a1,
                                         uint32_t a2, uint32_t a3,
                                         uint32_t b0, uint32_t b1) {
    asm volatile(
        "mma.sync.aligned.m16n8k16.row.col.f32.bf16.bf16.f32 "
        "{%0,%1,%2,%3}, {%4,%5,%6,%7}, {%8,%9}, {%0,%1,%2,%3};"
        : "+f"(c[0]), "+f"(c[1]), "+f"(c[2]), "+f"(c[3])
        : "r"(a0), "r"(a1), "r"(a2), "r"(a3), "r"(b0), "r"(b1));
}

template <bool GRAM>
__device__ __forceinline__ void gemm_body(const float* __restrict__ Af32,
                                          const __nv_bfloat16* __restrict__ Abf,
                                          const __nv_bfloat16* __restrict__ Bbf,
                                          const float* __restrict__ Pr,
                                          const float* __restrict__ W,
                                          int r_base, int c_base,
                                          __nv_bfloat16* sAb, __nv_bfloat16* sBb) {
    int tid  = threadIdx.x;             // 0..511
    int wid  = tid >> 5;
    int lane = tid & 31;
    int gid  = lane >> 2;
    int tid4 = lane & 3;
    int kg   = wid >> 3;                // 0..1 : K-split group
    int wm   = (wid >> 2) & 1;          // 0..1 : 32-row slice
    int wn   = wid & 3;                 // 0..3 : 32-col slice

    int lrow = (lane & 7) + ((lane >> 3) & 1) * 8;
    int lk8  = (lane >> 4) * 8;

    uint32_t sA_u0 = smem_u32(sAb);
    uint32_t sB_u0 = smem_u32(sBb);

    float4 rA[2];
    uint4  rAg;
    uint4  rB[2];

    auto load_regs = [&](int it) {
        int k0 = it * KT;
        #pragma unroll
        for (int q = 0; q < 2; q++) {
            int c = tid + q * 512;
            if (!GRAM)
                rA[q] = *(const float4*)&Af32[(size_t)(c >> 4) * NN + k0 + (c & 15) * 4];
            rB[q] = *(const uint4*)&Bbf[(size_t)(c >> 3) * NN + k0 + (c & 7) * 8];
        }
        if (GRAM)
            rAg = *(const uint4*)&Abf[(size_t)(tid >> 3) * NN + k0 + (tid & 7) * 8];
    };
    auto store_tile = [&](int buf) {
        __nv_bfloat16* sA = sAb + buf * SA_STAGE;
        __nv_bfloat16* sB = sBb + buf * SB_STAGE;
        if (!GRAM) {
            #pragma unroll
            for (int q = 0; q < 2; q++) {
                int c = tid + q * 512;
                __nv_bfloat162 lo = __floats2bfloat162_rn(rA[q].x, rA[q].y);
                __nv_bfloat162 hi = __floats2bfloat162_rn(rA[q].z, rA[q].w);
                uint2 o; o.x = *(uint32_t*)&lo; o.y = *(uint32_t*)&hi;
                *(uint2*)&sA[(c >> 4) * APAD + (c & 15) * 4] = o;
            }
        } else {
            *(uint4*)&sA[(tid >> 3) * APAD + (tid & 7) * 8] = rAg;
        }
        #pragma unroll
        for (int q = 0; q < 2; q++) {
            int c = tid + q * 512;
            *(uint4*)&sB[(c >> 3) * APAD + (c & 7) * 8] = rB[q];
        }
    };

    float acc[2][4][4] = {};   // [mi(16-row half)][n8][quad]

    const int NIT = NN / KT;   // 128

    load_regs(0);
    store_tile(0);
    load_regs(1);
    __syncthreads();

    for (int it = 0; it < NIT; it++) {
        if (it + 1 < NIT) store_tile((it + 1) & 1);
        if (it + 2 < NIT) load_regs(it + 2);

        uint32_t aU = sA_u0 + (it & 1) * (SA_STAGE * 2);
        uint32_t bU = sB_u0 + (it & 1) * (SB_STAGE * 2);

        #pragma unroll
        for (int step = 0; step < 2; step++) {
            int kk = kg * 32 + step * 16;
            uint32_t a0[4], a1[4];
            ldmx4(a0[0], a0[1], a0[2], a0[3],
                  aU + ((wm * 32 + lrow) * APAD + kk + lk8) * 2);
            ldmx4(a1[0], a1[1], a1[2], a1[3],
                  aU + ((wm * 32 + 16 + lrow) * APAD + kk + lk8) * 2);
            #pragma unroll
            for (int nj = 0; nj < 2; nj++) {
                uint32_t b0, b1, b2, b3;
                ldmx4(b0, b1, b2, b3,
                      bU + ((wn * 32 + nj * 16 + lrow) * APAD + kk + lk8) * 2);
                mma_bf16(acc[0][nj * 2 + 0], a0[0], a0[1], a0[2], a0[3], b0, b2);
                mma_bf16(acc[0][nj * 2 + 1], a0[0], a0[1], a0[2], a0[3], b1, b3);
                mma_bf16(acc[1][nj * 2 + 0], a1[0], a1[1], a1[2], a1[3], b0, b2);
                mma_bf16(acc[1][nj * 2 + 1], a1[0], a1[1], a1[2], a1[3], b1, b3);
            }
        }
        __syncthreads();
    }

    // ---- combine kg partials via smem (staging buffers are retired) ----
    float* comb = (float*)sAb;                 // 8 tiles x 1024 floats = 32 KB
    int tw = wm * 4 + wn;                      // warp tile id 0..7
    if (kg == 1) {
        float* dst = comb + tw * 1024 + lane * 32;
        #pragma unroll
        for (int mi = 0; mi < 2; mi++)
            #pragma unroll
            for (int ni = 0; ni < 4; ni++)
                #pragma unroll
                for (int j = 0; j < 4; j++)
                    dst[mi * 16 + ni * 4 + j] = acc[mi][ni][j];
    }
    __syncthreads();

    float s = 0.0f;
    if (kg == 0) {
        float* src = comb + tw * 1024 + lane * 32;
        #pragma unroll
        for (int mi = 0; mi < 2; mi++)
            #pragma unroll
            for (int ni = 0; ni < 4; ni++)
                #pragma unroll
                for (int j = 0; j < 4; j++)
                    acc[mi][ni][j] += src[mi * 16 + ni * 4 + j];

        #pragma unroll
        for (int mi = 0; mi < 2; mi++) {
            #pragma unroll
            for (int ni = 0; ni < 4; ni++) {
                int col = wn * 32 + ni * 8 + tid4 * 2;
                int m0  = wm * 32 + mi * 16 + gid;
                if (!GRAM) {
                    int m = r_base + m0;
                    float p00 = Pr[(size_t)m * PP + col];
                    float p01 = Pr[(size_t)m * PP + col + 1];
                    float p10 = Pr[(size_t)(m + 8) * PP + col];
                    float p11 = Pr[(size_t)(m + 8) * PP + col + 1];
                    float d0 = p00 - acc[mi][ni][0];
                    float d1 = p01 - acc[mi][ni][1];
                    float d2 = p10 - acc[mi][ni][2];
                    float d3 = p11 - acc[mi][ni][3];
                    s += d0 * d0 + d1 * d1 + d2 * d2 + d3 * d3;
                    float w00 = W[(size_t)m * PP + col];
                    float w01 = W[(size_t)m * PP + col + 1];
                    float w10 = W[(size_t)(m + 8) * PP + col];
                    float w11 = W[(size_t)(m + 8) * PP + col + 1];
                    float e0 = p00 - w00, e1 = p01 - w01;
                    float e2 = p10 - w10, e3 = p11 - w11;
                    s += e0 * e0 + e1 * e1 + e2 * e2 + e3 * e3;
                } else {
                    int r0g = r_base + m0;
                    int r1g = r0g + 8;
                    int c0g = c_base + col;
                    int c1g = c0g + 1;
                    float s00 = ((r0g < 128) == (c0g < 128)) ? 1.0f : -1.0f;
                    float s01 = ((r0g < 128) == (c1g < 128)) ? 1.0f : -1.0f;
                    float s10 = ((r1g < 128) == (c0g < 128)) ? 1.0f : -1.0f;
                    float s11 = ((r1g < 128) == (c1g < 128)) ? 1.0f : -1.0f;
                    s += s00 * acc[mi][ni][0] * acc[mi][ni][0]
                       + s01 * acc[mi][ni][1] * acc[mi][ni][1]
                       + s10 * acc[mi][ni][2] * acc[mi][ni][2]
                       + s11 * acc[mi][ni][3] * acc[mi][ni][3];
                }
            }
        }
    }
    s = block_reduce_sum(s);
    if (tid == 0) atomicAdd(&g_acc[GRAM ? 0 : 1], (double)s);
}

__global__ void __launch_bounds__(512) k_main(const float* __restrict__ A,
                                              const float* __restrict__ Pr,
                                              const float* __restrict__ W,
                                              float* __restrict__ out) {
    extern __shared__ __align__(16) char dynsm[];
    __nv_bfloat16* sAb = (__nv_bfloat16*)dynsm;
    __nv_bfloat16* sBb = (__nv_bfloat16*)(dynsm + SA_STAGE * 2 * 2);

    int bid = blockIdx.x;
    if (bid < STRUCT_BLOCKS) {
        gemm_body<false>(A + (size_t)bid * 64 * NN, nullptr, g_Mt, Pr, W,
                         bid * 64, 0, sAb, sBb);
    } else {
        int g = bid - STRUCT_BLOCKS;
        int rblk = g / 3, cblk = g % 3;
        gemm_body<true>(nullptr,
                        g_Mt + (size_t)(rblk * 64) * NN,
                        g_Mt + (size_t)(cblk * 128) * NN,
                        Pr, nullptr, rblk * 64, cblk * 128, sAb, sBb);
    }

    __shared__ unsigned int s_ticket;
    __threadfence();
    if (threadIdx.x == 0) s_ticket = atomicAdd(&g_done, 1u);
    __syncthreads();
    if (s_ticket == GRID_MAIN - 1) {
        if (threadIdx.x == 0) {
            double nn = (double)NN * (double)NN;
            double np = (double)NN * (double)PP;
            out[0] = (float)(g_acc[0] / nn + g_acc[1] / np);
            g_done = 0u;
        }
    }
}

// ---------------------------------------------------------------------------
extern "C" void kernel_launch(void* const* d_in, const int* in_sizes, int n_in,
                              void* d_out, int out_size) {
    const float* preds = (const float*)d_in[0];   // [8192, 128]
    const float* emb   = (const float*)d_in[1];   // [8192, 256]
    const float* adj   = (const float*)d_in[2];   // [8192, 8192]
    const float* wts   = (const float*)d_in[3];   // [8192, 128]
    float* out = (float*)d_out;

    // idempotent; capture-safe (no alloc, no sync)
    cudaFuncSetAttribute(k_prep, cudaFuncAttributeMaxDynamicSharedMemorySize, SMEM_PREP);
    cudaFuncSetAttribute(k_main, cudaFuncAttributeMaxDynamicSharedMemorySize, SMEM_MAIN);

    k_prep<<<PREP_GRID, 256, SMEM_PREP>>>(emb, preds);
    k_main<<<GRID_MAIN, 512, SMEM_MAIN>>>(adj, preds, wts, out);
}

// round 14
// speedup vs baseline: 1.1659x; 1.0349x over previous
#include <cuda_runtime.h>
#include <cuda_bf16.h>
#include <math.h>
#include <stdint.h>

#define NN 8192
#define PP 128
#define DD 256

// ---------------- device scratch (static globals — no runtime alloc) ----------
__device__ __nv_bfloat16 g_Mt[384 * NN];            // Mᵀ bf16: rows 0-127 = Pᵀ, 128-383 = Xnᵀ
__device__ double g_acc[2];                         // 0: coherence, 1: structure+weight SSE
__device__ unsigned int g_sync;                     // phase barrier (reset by finisher)
__device__ unsigned int g_done;                     // finisher ticket (reset by finisher)

// ---------------------------------------------------------------------------
__device__ __forceinline__ uint32_t smem_u32(const void* p) {
    return (uint32_t)__cvta_generic_to_shared(p);
}

__device__ __forceinline__ float block_reduce_sum(float v) {
    __shared__ float red[16];
    int lane = threadIdx.x & 31;
    int wid  = threadIdx.x >> 5;
    #pragma unroll
    for (int o = 16; o > 0; o >>= 1) v += __shfl_xor_sync(0xffffffffu, v, o);
    if (lane == 0) red[wid] = v;
    __syncthreads();
    if (wid == 0) {
        int nw = (int)blockDim.x >> 5;
        v = (lane < nw) ? red[lane] : 0.0f;
        #pragma unroll
        for (int o = 8; o > 0; o >>= 1) v += __shfl_xor_sync(0xffffffffu, v, o);
    }
    return v;
}

// ---------------------------------------------------------------------------
#define STRUCT_BLOCKS 128
#define GRAM_BLOCKS 18
#define GRID_MAIN (STRUCT_BLOCKS + GRAM_BLOCKS)    // 146 <= 148 SMs: one wave

#define KT 64
#define APAD 72
#define SA_STAGE (64 * APAD)
#define SB_STAGE (128 * APAD)
#define SMEM_GEMM ((SA_STAGE + SB_STAGE) * 2 * 2)  // 55296
#define XS 259
#define SMEM_PREPF (64 * XS * 4 + 64 * 4)          // 66560
#define SMEM_ALL (SMEM_PREPF > SMEM_GEMM ? SMEM_PREPF : SMEM_GEMM)

#define PREP_TASKS 384     // 128 X-slabs + 256 P-tiles

__device__ __forceinline__ void ldmx4(uint32_t& r0, uint32_t& r1, uint32_t& r2,
                                      uint32_t& r3, uint32_t addr) {
    asm volatile("ldmatrix.sync.aligned.m8n8.x4.shared.b16 {%0,%1,%2,%3}, [%4];"
                 : "=r"(r0), "=r"(r1), "=r"(r2), "=r"(r3) : "r"(addr));
}
__device__ __forceinline__ void mma_bf16(float* c, uint32_t a0, uint32_t a1,
                                         uint32_t a2, uint32_t a3,
                                         uint32_t b0, uint32_t b1) {
    asm volatile(
        "mma.sync.aligned.m16n8k16.row.col.f32.bf16.bf16.f32 "
        "{%0,%1,%2,%3}, {%4,%5,%6,%7}, {%8,%9}, {%0,%1,%2,%3};"
        : "+f"(c[0]), "+f"(c[1]), "+f"(c[2]), "+f"(c[3])
        : "r"(a0), "r"(a1), "r"(a2), "r"(a3), "r"(b0), "r"(b1));
}

// ---- prep task bodies (512 threads) ----------------------------------------
__device__ __forceinline__ void prep_xslab(const float* __restrict__ X,
                                           char* dynsm, int xs) {
    int t = threadIdx.x;
    int lane = t & 31;
    int wrp  = t >> 5;
    int tx = t & 15;
    int ty2 = t >> 4;                  // 0..31
    float* tt = (float*)dynsm;
    float* sI = (float*)(dynsm + 64 * XS * 4);
    int kb = xs * 64;

    #pragma unroll
    for (int q = 0; q < 8; q++) {
        int c = t + q * 512;
        int row = c >> 6;
        int col = (c & 63) * 4;
        float4 v = *(const float4*)&X[(size_t)(kb + row) * DD + col];
        tt[row * XS + col + 0] = v.x;
        tt[row * XS + col + 1] = v.y;
        tt[row * XS + col + 2] = v.z;
        tt[row * XS + col + 3] = v.w;
    }
    __syncthreads();

    #pragma unroll
    for (int r4 = 0; r4 < 4; r4++) {
        int row = wrp * 4 + r4;
        float ss = 0.0f;
        #pragma unroll
        for (int j = 0; j < 8; j++) {
            float x = tt[row * XS + lane * 8 + j];
            ss += x * x;
        }
        #pragma unroll
        for (int o = 16; o > 0; o >>= 1) ss += __shfl_xor_sync(0xffffffffu, ss, o);
        if (lane == 0) sI[row] = 1.0f / fmaxf(sqrtf(ss), 1e-8f);
    }
    __syncthreads();

    #pragma unroll
    for (int dt = 0; dt < 4; dt++) {
        #pragma unroll
        for (int rr = ty2; rr < 64; rr += 32) {
            int cc = tx * 4;
            int sc = dt * 64 + rr;
            float f0 = tt[(cc + 0) * XS + sc] * sI[cc + 0];
            float f1 = tt[(cc + 1) * XS + sc] * sI[cc + 1];
            float f2 = tt[(cc + 2) * XS + sc] * sI[cc + 2];
            float f3 = tt[(cc + 3) * XS + sc] * sI[cc + 3];
            __nv_bfloat162 lo = __floats2bfloat162_rn(f0, f1);
            __nv_bfloat162 hi = __floats2bfloat162_rn(f2, f3);
            uint2 o; o.x = *(uint32_t*)&lo; o.y = *(uint32_t*)&hi;
            *(uint2*)&g_Mt[(size_t)(128 + dt * 64 + rr) * NN + kb + cc] = o;
        }
    }
}

__device__ __forceinline__ void prep_ptile(const float* __restrict__ Pr,
                                           char* dynsm, int pt) {
    int t = threadIdx.x;
    int tx = t & 15;
    int ty2 = t >> 4;                  // 0..31
    float (*tt65)[65] = (float(*)[65])dynsm;
    int kb = (pt >> 1) * 64;
    int pb = (pt & 1) * 64;
    #pragma unroll
    for (int r = ty2; r < 64; r += 32) {
        float4 v = *(const float4*)&Pr[(size_t)(kb + r) * PP + pb + tx * 4];
        tt65[r][tx * 4 + 0] = v.x;
        tt65[r][tx * 4 + 1] = v.y;
        tt65[r][tx * 4 + 2] = v.z;
        tt65[r][tx * 4 + 3] = v.w;
    }
    __syncthreads();
    #pragma unroll
    for (int rr = ty2; rr < 64; rr += 32) {
        int cc = tx * 4;
        __nv_bfloat162 lo = __floats2bfloat162_rn(tt65[cc + 0][rr], tt65[cc + 1][rr]);
        __nv_bfloat162 hi = __floats2bfloat162_rn(tt65[cc + 2][rr], tt65[cc + 3][rr]);
        uint2 o; o.x = *(uint32_t*)&lo; o.y = *(uint32_t*)&hi;
        *(uint2*)&g_Mt[(size_t)(pb + rr) * NN + kb + cc] = o;
    }
}

// ---- GEMM body (R11 geometry: 16 warps, warp tile 16x32) --------------------
template <bool GRAM>
__device__ __forceinline__ void gemm_body(const float* __restrict__ Af32,
                                          const __nv_bfloat16* __restrict__ Abf,
                                          const __nv_bfloat16* __restrict__ Bbf,
                                          const float* __restrict__ Pr,
                                          const float* __restrict__ W,
                                          int r_base, int c_base,
                                          __nv_bfloat16* sAb, __nv_bfloat16* sBb) {
    int tid  = threadIdx.x;
    int wid  = tid >> 5;
    int lane = tid & 31;
    int gid  = lane >> 2;
    int tid4 = lane & 3;
    int wm   = wid >> 2;
    int wn   = wid & 3;

    int lrow = (lane & 7) + ((lane >> 3) & 1) * 8;
    int lk8  = (lane >> 4) * 8;

    uint32_t sA_u0 = smem_u32(sAb);
    uint32_t sB_u0 = smem_u32(sBb);

    float4 rA[2];
    uint4  rAg;
    uint4  rB[2];

    auto load_regs = [&](int it) {
        int k0 = it * KT;
        #pragma unroll
        for (int q = 0; q < 2; q++) {
            int c = tid + q * 512;
            if (!GRAM)
                rA[q] = *(const float4*)&Af32[(size_t)(c >> 4) * NN + k0 + (c & 15) * 4];
            rB[q] = *(const uint4*)&Bbf[(size_t)(c >> 3) * NN + k0 + (c & 7) * 8];
        }
        if (GRAM)
            rAg = *(const uint4*)&Abf[(size_t)(tid >> 3) * NN + k0 + (tid & 7) * 8];
    };
    auto store_tile = [&](int buf) {
        __nv_bfloat16* sA = sAb + buf * SA_STAGE;
        __nv_bfloat16* sB = sBb + buf * SB_STAGE;
        if (!GRAM) {
            #pragma unroll
            for (int q = 0; q < 2; q++) {
                int c = tid + q * 512;
                __nv_bfloat162 lo = __floats2bfloat162_rn(rA[q].x, rA[q].y);
                __nv_bfloat162 hi = __floats2bfloat162_rn(rA[q].z, rA[q].w);
                uint2 o; o.x = *(uint32_t*)&lo; o.y = *(uint32_t*)&hi;
                *(uint2*)&sA[(c >> 4) * APAD + (c & 15) * 4] = o;
            }
        } else {
            *(uint4*)&sA[(tid >> 3) * APAD + (tid & 7) * 8] = rAg;
        }
        #pragma unroll
        for (int q = 0; q < 2; q++) {
            int c = tid + q * 512;
            *(uint4*)&sB[(c >> 3) * APAD + (c & 7) * 8] = rB[q];
        }
    };

    float acc[4][4] = {};

    const int NIT = NN / KT;

    load_regs(0);
    store_tile(0);
    load_regs(1);
    __syncthreads();

    for (int it = 0; it < NIT; it++) {
        if (it + 1 < NIT) store_tile((it + 1) & 1);
        if (it + 2 < NIT) load_regs(it + 2);

        uint32_t aU = sA_u0 + (it & 1) * (SA_STAGE * 2);
        uint32_t bU = sB_u0 + (it & 1) * (SB_STAGE * 2);

        #pragma unroll
        for (int kk = 0; kk < KT; kk += 16) {
            uint32_t a0, a1, a2, a3;
            ldmx4(a0, a1, a2, a3,
                  aU + ((wm * 16 + lrow) * APAD + kk + lk8) * 2);
            #pragma unroll
            for (int nj = 0; nj < 2; nj++) {
                uint32_t b0, b1, b2, b3;
                ldmx4(b0, b1, b2, b3,
                      bU + ((wn * 32 + nj * 16 + lrow) * APAD + kk + lk8) * 2);
                mma_bf16(acc[nj * 2 + 0], a0, a1, a2, a3, b0, b2);
                mma_bf16(acc[nj * 2 + 1], a0, a1, a2, a3, b1, b3);
            }
        }
        __syncthreads();
    }

    float s = 0.0f;
    #pragma unroll
    for (int ni = 0; ni < 4; ni++) {
        int col = wn * 32 + ni * 8 + tid4 * 2;
        int m0  = wm * 16 + gid;
        if (!GRAM) {
            int m = r_base + m0;
            float p00 = Pr[(size_t)m * PP + col];
            float p01 = Pr[(size_t)m * PP + col + 1];
            float p10 = Pr[(size_t)(m + 8) * PP + col];
            float p11 = Pr[(size_t)(m + 8) * PP + col + 1];
            float d0 = p00 - acc[ni][0];
            float d1 = p01 - acc[ni][1];
            float d2 = p10 - acc[ni][2];
            float d3 = p11 - acc[ni][3];
            s += d0 * d0 + d1 * d1 + d2 * d2 + d3 * d3;
            float w00 = W[(size_t)m * PP + col];
            float w01 = W[(size_t)m * PP + col + 1];
            float w10 = W[(size_t)(m + 8) * PP + col];
            float w11 = W[(size_t)(m + 8) * PP + col + 1];
            float e0 = p00 - w00, e1 = p01 - w01, e2 = p10 - w10, e3 = p11 - w11;
            s += e0 * e0 + e1 * e1 + e2 * e2 + e3 * e3;
        } else {
            int r0g = r_base + m0;
            int r1g = r0g + 8;
            int c0g = c_base + col;
            int c1g = c0g + 1;
            float s00 = ((r0g < 128) == (c0g < 128)) ? 1.0f : -1.0f;
            float s01 = ((r0g < 128) == (c1g < 128)) ? 1.0f : -1.0f;
            float s10 = ((r1g < 128) == (c0g < 128)) ? 1.0f : -1.0f;
            float s11 = ((r1g < 128) == (c1g < 128)) ? 1.0f : -1.0f;
            s += s00 * acc[ni][0] * acc[ni][0] + s01 * acc[ni][1] * acc[ni][1]
               + s10 * acc[ni][2] * acc[ni][2] + s11 * acc[ni][3] * acc[ni][3];
        }
    }
    s = block_reduce_sum(s);
    if (tid == 0) atomicAdd(&g_acc[GRAM ? 0 : 1], (double)s);
}

// ---------------------------------------------------------------------------
__global__ void __launch_bounds__(512) k_all(const float* __restrict__ A,
                                             const float* __restrict__ Pr,
                                             const float* __restrict__ X,
                                             const float* __restrict__ W,
                                             float* __restrict__ out) {
    extern __shared__ __align__(16) char dynsm[];
    int bid = blockIdx.x;
    int tid = threadIdx.x;

    // ---- phase 1: prep (tasks strided over the 146 resident CTAs) ----
    if (bid == 0 && tid < 2) g_acc[tid] = 0.0;
    for (int task = bid; task < PREP_TASKS; task += GRID_MAIN) {
        if (task < 128) prep_xslab(X, dynsm, task);
        else            prep_ptile(Pr, dynsm, task - 128);
        __syncthreads();   // smem reuse across tasks
    }

    // ---- grid barrier (all 146 CTAs resident: grid <= SM count, 1 CTA/SM) ----
    __threadfence();
    __syncthreads();
    if (tid == 0) {
        atomicAdd(&g_sync, 1u);
        while (atomicAdd(&g_sync, 0u) < GRID_MAIN) { }
    }
    __syncthreads();
    __threadfence();

    // ---- phase 2: GEMM ----
    __nv_bfloat16* sAb = (__nv_bfloat16*)dynsm;
    __nv_bfloat16* sBb = (__nv_bfloat16*)(dynsm + SA_STAGE * 2 * 2);

    if (bid < STRUCT_BLOCKS) {
        gemm_body<false>(A + (size_t)bid * 64 * NN, nullptr, g_Mt, Pr, W,
                         bid * 64, 0, sAb, sBb);
    } else {
        int g = bid - STRUCT_BLOCKS;
        int rblk = g / 3, cblk = g % 3;
        gemm_body<true>(nullptr,
                        g_Mt + (size_t)(rblk * 64) * NN,
                        g_Mt + (size_t)(cblk * 128) * NN,
                        Pr, nullptr, rblk * 64, cblk * 128, sAb, sBb);
    }

    // ---- finisher ----
    __shared__ unsigned int s_ticket;
    __threadfence();
    if (tid == 0) s_ticket = atomicAdd(&g_done, 1u);
    __syncthreads();
    if (s_ticket == GRID_MAIN - 1) {
        if (tid == 0) {
            double nn = (double)NN * (double)NN;
            double np = (double)NN * (double)PP;
            out[0] = (float)(g_acc[0] / nn + g_acc[1] / np);
            g_done = 0u;
            g_sync = 0u;
        }
    }
}

// ---------------------------------------------------------------------------
extern "C" void kernel_launch(void* const* d_in, const int* in_sizes, int n_in,
                              void* d_out, int out_size) {
    const float* preds = (const float*)d_in[0];   // [8192, 128]
    const float* emb   = (const float*)d_in[1];   // [8192, 256]
    const float* adj   = (const float*)d_in[2];   // [8192, 8192]
    const float* wts   = (const float*)d_in[3];   // [8192, 128]
    float* out = (float*)d_out;

    // idempotent; capture-safe (no alloc, no sync)
    cudaFuncSetAttribute(k_all, cudaFuncAttributeMaxDynamicSharedMemorySize, SMEM_ALL);

    k_all<<<GRID_MAIN, 512, SMEM_ALL>>>(adj, preds, emb, wts, out);
}